// round 1
// baseline (speedup 1.0000x reference)
#include <cuda_runtime.h>
#include <math.h>

#define T_STEPS 512
#define BATCH   64
#define IN_DIM  1024
#define HID     1024

// ============================================================
// Kernel 1: Xp = X @ W_xh + b     (M=32768, N=1024, K=1024)
// 64x64 block tile, BK=16, 256 threads, 4x4 micro-tile.
// ============================================================
#define G1_BM 64
#define G1_BN 64
#define G1_BK 16

__global__ __launch_bounds__(256) void xp_gemm(const float* __restrict__ A,
                                               const float* __restrict__ B,
                                               const float* __restrict__ bias,
                                               float* __restrict__ C) {
    __shared__ float As[G1_BK][G1_BM];      // transposed A tile
    __shared__ float Bs[G1_BK][G1_BN];
    const int bm = blockIdx.y * G1_BM;
    const int bn = blockIdx.x * G1_BN;
    const int tid = threadIdx.x;
    const int tx = tid & 15;   // n direction
    const int ty = tid >> 4;   // m direction

    float acc[4][4] = {};

    for (int k0 = 0; k0 < IN_DIM; k0 += G1_BK) {
        // Load A tile 64x16 (each thread: one float4 of a row, store transposed)
        {
            int m  = tid >> 2;             // 0..63
            int kq = (tid & 3) * 4;        // 0,4,8,12
            float4 v = *reinterpret_cast<const float4*>(
                &A[(size_t)(bm + m) * IN_DIM + k0 + kq]);
            As[kq + 0][m] = v.x;
            As[kq + 1][m] = v.y;
            As[kq + 2][m] = v.z;
            As[kq + 3][m] = v.w;
        }
        // Load B tile 16x64 (each thread: one float4)
        {
            int kk = tid >> 4;             // 0..15
            int n  = (tid & 15) * 4;       // 0..60
            *reinterpret_cast<float4*>(&Bs[kk][n]) =
                *reinterpret_cast<const float4*>(
                    &B[(size_t)(k0 + kk) * HID + bn + n]);
        }
        __syncthreads();
        #pragma unroll
        for (int k = 0; k < G1_BK; k++) {
            float4 a4 = *reinterpret_cast<const float4*>(&As[k][ty * 4]);
            float4 b4 = *reinterpret_cast<const float4*>(&Bs[k][tx * 4]);
            float a[4] = {a4.x, a4.y, a4.z, a4.w};
            float b[4] = {b4.x, b4.y, b4.z, b4.w};
            #pragma unroll
            for (int i = 0; i < 4; i++)
                #pragma unroll
                for (int j = 0; j < 4; j++)
                    acc[i][j] += a[i] * b[j];
        }
        __syncthreads();
    }

    #pragma unroll
    for (int i = 0; i < 4; i++) {
        int m = bm + ty * 4 + i;
        #pragma unroll
        for (int j = 0; j < 4; j++) {
            int n = bn + tx * 4 + j;
            C[(size_t)m * HID + n] = acc[i][j] + bias[n];
        }
    }
}

// ============================================================
// Kernel 2: t = 0 step:  out0 = tanh(Xp_0)   (elementwise)
// ============================================================
__global__ void tanh_inplace(float* __restrict__ p, int n) {
    int i = blockIdx.x * blockDim.x + threadIdx.x;
    if (i < n) p[i] = tanhf(p[i]);
}

// ============================================================
// Kernel 3: scan step:  out_t = tanh(Xp_t + h @ W_hh)
// h = d_out slice (t-1), Xp_t = d_out slice t (in place).
// BM=64 (all of batch), BN=8 -> 128 blocks. 128 threads,
// each thread computes 4 rows x 1 col. BK=32.
// ============================================================
#define G2_BN 8
#define G2_BK 32
#define AS_STRIDE 68   // 64 + 4 pad: float4-aligned, 4-way store conflicts only

__global__ __launch_bounds__(128) void rnn_step(const float* __restrict__ h,
                                                const float* __restrict__ W,
                                                float* __restrict__ io /* Xp_t in, h_t out */) {
    __shared__ float As[G2_BK][AS_STRIDE];  // transposed h tile [k][m]
    __shared__ float Bs[G2_BK][G2_BN];
    const int bn  = blockIdx.x * G2_BN;
    const int tid = threadIdx.x;
    const int tx  = tid & 7;    // n
    const int ty  = tid >> 3;   // m group (0..15)

    float acc[4] = {};

    for (int k0 = 0; k0 < HID; k0 += G2_BK) {
        // Load h tile 64 x 32 -> transposed. 512 float4s / 128 threads = 4 each.
        #pragma unroll
        for (int j = 0; j < 4; j++) {
            int idx = tid + j * 128;       // 0..511
            int m   = idx >> 3;            // 0..63
            int kq  = (idx & 7) * 4;       // 0..28
            float4 v = *reinterpret_cast<const float4*>(
                &h[(size_t)m * HID + k0 + kq]);
            As[kq + 0][m] = v.x;
            As[kq + 1][m] = v.y;
            As[kq + 2][m] = v.z;
            As[kq + 3][m] = v.w;
        }
        // Load W tile 32 x 8. 256 elems / 128 threads = 2 each.
        #pragma unroll
        for (int j = 0; j < 2; j++) {
            int idx = tid + j * 128;       // 0..255
            int kk  = idx >> 3;            // 0..31
            int n   = idx & 7;
            Bs[kk][n] = W[(size_t)(k0 + kk) * HID + bn + n];
        }
        __syncthreads();
        #pragma unroll
        for (int k = 0; k < G2_BK; k++) {
            float4 a4 = *reinterpret_cast<const float4*>(&As[k][ty * 4]);
            float  b  = Bs[k][tx];
            acc[0] += a4.x * b;
            acc[1] += a4.y * b;
            acc[2] += a4.z * b;
            acc[3] += a4.w * b;
        }
        __syncthreads();
    }

    #pragma unroll
    for (int i = 0; i < 4; i++) {
        int m = ty * 4 + i;
        size_t off = (size_t)m * HID + bn + tx;
        io[off] = tanhf(acc[i] + io[off]);
    }
}

// ============================================================
// Kernel 4: copy final state (slice T-1) to the tail of d_out
// ============================================================
__global__ void copy_final(const float* __restrict__ src, float* __restrict__ dst, int n) {
    int i = blockIdx.x * blockDim.x + threadIdx.x;
    if (i < n) dst[i] = src[i];
}

// ============================================================
extern "C" void kernel_launch(void* const* d_in, const int* in_sizes, int n_in,
                              void* d_out, int out_size) {
    const float* X    = (const float*)d_in[0];   // [T,B,I]
    const float* W_xh = (const float*)d_in[1];   // [I,H]
    const float* W_hh = (const float*)d_in[2];   // [H,H]
    const float* b_h  = (const float*)d_in[3];   // [H]
    float* out = (float*)d_out;                  // [T,B,H] outputs (+ [B,H] final state)

    const int BH = BATCH * HID;                  // 65536 elems per timestep slice

    // 1) Xp = X @ W_xh + b  -> written straight into d_out
    {
        dim3 grid(HID / G1_BN, (T_STEPS * BATCH) / G1_BM);
        xp_gemm<<<grid, 256>>>(X, W_xh, b_h, out);
    }

    // 2) step 0: h_0 = tanh(Xp_0)
    tanh_inplace<<<(BH + 255) / 256, 256>>>(out, BH);

    // 3) steps 1..T-1 (in place): out_t = tanh(Xp_t + out_{t-1} @ W_hh)
    for (int t = 1; t < T_STEPS; t++) {
        const float* h = out + (size_t)(t - 1) * BH;
        float* io      = out + (size_t)t * BH;
        rnn_step<<<HID / G2_BN, 128>>>(h, W_hh, io);
    }

    // 4) final_state = outputs[T-1]  (appended after outputs if room)
    if (out_size >= T_STEPS * BH + BH) {
        copy_final<<<(BH + 255) / 256, 256>>>(out + (size_t)(T_STEPS - 1) * BH,
                                              out + (size_t)T_STEPS * BH, BH);
    }
}

// round 2
// speedup vs baseline: 2.6448x; 2.6448x over previous
#include <cuda_runtime.h>
#include <math.h>

#define T_STEPS 512
#define BATCH   64
#define IN_DIM  1024
#define HID     1024
#define BH      (BATCH * HID)          // 65536

// ============================================================
// Kernel 1: Xp = X @ W_xh + b     (M=32768, N=1024, K=1024)
// ============================================================
#define G1_BM 64
#define G1_BN 64
#define G1_BK 16

__global__ __launch_bounds__(256) void xp_gemm(const float* __restrict__ A,
                                               const float* __restrict__ B,
                                               const float* __restrict__ bias,
                                               float* __restrict__ C) {
    __shared__ float As[G1_BK][G1_BM];
    __shared__ float Bs[G1_BK][G1_BN];
    const int bm = blockIdx.y * G1_BM;
    const int bn = blockIdx.x * G1_BN;
    const int tid = threadIdx.x;
    const int tx = tid & 15;
    const int ty = tid >> 4;

    float acc[4][4] = {};

    for (int k0 = 0; k0 < IN_DIM; k0 += G1_BK) {
        {
            int m  = tid >> 2;
            int kq = (tid & 3) * 4;
            float4 v = *reinterpret_cast<const float4*>(
                &A[(size_t)(bm + m) * IN_DIM + k0 + kq]);
            As[kq + 0][m] = v.x;
            As[kq + 1][m] = v.y;
            As[kq + 2][m] = v.z;
            As[kq + 3][m] = v.w;
        }
        {
            int kk = tid >> 4;
            int n  = (tid & 15) * 4;
            *reinterpret_cast<float4*>(&Bs[kk][n]) =
                *reinterpret_cast<const float4*>(
                    &B[(size_t)(k0 + kk) * HID + bn + n]);
        }
        __syncthreads();
        #pragma unroll
        for (int k = 0; k < G1_BK; k++) {
            float4 a4 = *reinterpret_cast<const float4*>(&As[k][ty * 4]);
            float4 b4 = *reinterpret_cast<const float4*>(&Bs[k][tx * 4]);
            float a[4] = {a4.x, a4.y, a4.z, a4.w};
            float b[4] = {b4.x, b4.y, b4.z, b4.w};
            #pragma unroll
            for (int i = 0; i < 4; i++)
                #pragma unroll
                for (int j = 0; j < 4; j++)
                    acc[i][j] += a[i] * b[j];
        }
        __syncthreads();
    }

    #pragma unroll
    for (int i = 0; i < 4; i++) {
        int m = bm + ty * 4 + i;
        #pragma unroll
        for (int j = 0; j < 4; j++) {
            int n = bn + tx * 4 + j;
            C[(size_t)m * HID + n] = acc[i][j] + bias[n];
        }
    }
}

// ============================================================
// Persistent scan kernel: all 512 steps in one launch.
// Grid = 128 blocks = 8 K-slices x 16 N-blocks, 256 threads.
// Phase A: partial[ks] = h_{t-1}[:, kslice] @ W_hh[kslice, nslice]
// Phase B: out[t] = tanh(Xp_t + sum_ks partial[ks])   (in place)
// Software grid barrier between phases (all blocks co-resident).
// ============================================================
#define SC_BLOCKS 128
#define SC_KS     8        // K splits
#define SC_KSL    128      // K per slice
#define SC_NC     64       // N cols per block
#define SC_CH     64       // staged h chunk (k direction)

__device__ float    g_partial[SC_KS * BH];   // 2 MB scratch
__device__ unsigned g_bar  = 0;
__device__ unsigned g_done = 0;

__device__ __forceinline__ void grid_bar(unsigned* cnt, int nblocks) {
    __syncthreads();
    (*cnt)++;
    if (threadIdx.x == 0) {
        __threadfence();
        atomicAdd(&g_bar, 1u);
        unsigned target = (unsigned)nblocks * (*cnt);
        while (*((volatile unsigned*)&g_bar) < target) { }
        __threadfence();
    }
    __syncthreads();
}

__global__ __launch_bounds__(256, 1) void rnn_scan(const float* __restrict__ W,
                                                   float* __restrict__ out) {
    __shared__ float Ws[SC_KSL][SC_NC];   // 32 KB  (W_hh slice, [k][n])
    __shared__ float hT[SC_CH][64];       // 16 KB  (h chunk, transposed [k][b])

    const int tid = threadIdx.x;
    const int bid = blockIdx.x;
    const int ks  = bid >> 4;             // 0..7
    const int nb  = bid & 15;             // 0..15
    const int k_base = ks * SC_KSL;
    const int n_base = nb * SC_NC;
    const int ty = tid >> 4;              // 0..15  (b-group: rows 4ty..4ty+3)
    const int tx = tid & 15;              // 0..15  (n-group: cols tx+16j)

    // Load this block's W_hh slice once for all 512 steps.
    #pragma unroll
    for (int j = 0; j < 8; j++) {
        int idx = tid + j * 256;          // 0..2047
        int r   = idx >> 4;               // 0..127
        int c4  = (idx & 15) * 4;         // 0..60
        *reinterpret_cast<float4*>(&Ws[r][c4]) =
            *reinterpret_cast<const float4*>(
                &W[(size_t)(k_base + r) * HID + n_base + c4]);
    }

    unsigned barcnt = 0;

    // Step 0: h_0 = tanh(Xp_0), elementwise over out[0..BH)
    {
        int base = (bid * 256 + tid) * 2;     // 0..65534, even
        float2 v = *reinterpret_cast<float2*>(&out[base]);
        v.x = tanhf(v.x);
        v.y = tanhf(v.y);
        *reinterpret_cast<float2*>(&out[base]) = v;
    }
    grid_bar(&barcnt, SC_BLOCKS);

    for (int t = 1; t < T_STEPS; t++) {
        const float* h = out + (size_t)(t - 1) * BH;

        // ---------- Phase A: partial GEMM over this block's k-slice ----------
        float acc[4][4] = {};

        #pragma unroll
        for (int chunk = 0; chunk < SC_KSL / SC_CH; chunk++) {
            const int k0 = k_base + chunk * SC_CH;
            // Stage hT[64k][64b]: conflict-free STS; strided global reads
            // (h lives in L2; sector traffic is small).
            #pragma unroll
            for (int j = 0; j < 4; j++) {
                int idx = tid + j * 256;      // 0..1023
                int c   = idx >> 6;           // 0..15 (k quad)
                int b   = idx & 63;           // 0..63
                float4 v = *reinterpret_cast<const float4*>(
                    &h[(size_t)b * HID + k0 + c * 4]);
                hT[c * 4 + 0][b] = v.x;
                hT[c * 4 + 1][b] = v.y;
                hT[c * 4 + 2][b] = v.z;
                hT[c * 4 + 3][b] = v.w;
            }
            __syncthreads();

            const int kw = chunk * SC_CH;
            #pragma unroll 8
            for (int kk = 0; kk < SC_CH; kk++) {
                float4 hv = *reinterpret_cast<const float4*>(&hT[kk][ty * 4]);
                float w0 = Ws[kw + kk][tx];
                float w1 = Ws[kw + kk][tx + 16];
                float w2 = Ws[kw + kk][tx + 32];
                float w3 = Ws[kw + kk][tx + 48];
                acc[0][0] += hv.x * w0; acc[0][1] += hv.x * w1;
                acc[0][2] += hv.x * w2; acc[0][3] += hv.x * w3;
                acc[1][0] += hv.y * w0; acc[1][1] += hv.y * w1;
                acc[1][2] += hv.y * w2; acc[1][3] += hv.y * w3;
                acc[2][0] += hv.z * w0; acc[2][1] += hv.z * w1;
                acc[2][2] += hv.z * w2; acc[2][3] += hv.z * w3;
                acc[3][0] += hv.w * w0; acc[3][1] += hv.w * w1;
                acc[3][2] += hv.w * w2; acc[3][3] += hv.w * w3;
            }
            __syncthreads();
        }

        // Store partials
        #pragma unroll
        for (int i = 0; i < 4; i++) {
            int b = ty * 4 + i;
            #pragma unroll
            for (int j = 0; j < 4; j++) {
                int n = n_base + tx + 16 * j;
                g_partial[ks * BH + b * HID + n] = acc[i][j];
            }
        }
        grid_bar(&barcnt, SC_BLOCKS);

        // ---------- Phase B: reduce + tanh (in place into out[t]) ----------
        {
            int base = (bid * 256 + tid) * 2;
            float* o = out + (size_t)t * BH;
            float2 xp = *reinterpret_cast<float2*>(&o[base]);
            float s0 = xp.x, s1 = xp.y;
            #pragma unroll
            for (int k2 = 0; k2 < SC_KS; k2++) {
                float2 p = *reinterpret_cast<const float2*>(&g_partial[k2 * BH + base]);
                s0 += p.x; s1 += p.y;
            }
            float2 r;
            r.x = tanhf(s0);
            r.y = tanhf(s1);
            *reinterpret_cast<float2*>(&o[base]) = r;
        }
        grid_bar(&barcnt, SC_BLOCKS);
    }

    // Final state = out[T-1], copied to the tail.
    {
        int base = (bid * 256 + tid) * 2;
        float2 v = *reinterpret_cast<const float2*>(
            &out[(size_t)(T_STEPS - 1) * BH + base]);
        *reinterpret_cast<float2*>(&out[(size_t)T_STEPS * BH + base]) = v;
    }

    // Reset barrier state for the next (graph-replayed) call.
    __syncthreads();
    if (tid == 0) {
        unsigned d = atomicAdd(&g_done, 1u);
        if (d == (unsigned)(gridDim.x - 1)) {
            g_bar  = 0;
            g_done = 0;
            __threadfence();
        }
    }
}

// ============================================================
extern "C" void kernel_launch(void* const* d_in, const int* in_sizes, int n_in,
                              void* d_out, int out_size) {
    const float* X    = (const float*)d_in[0];   // [T,B,I]
    const float* W_xh = (const float*)d_in[1];   // [I,H]
    const float* W_hh = (const float*)d_in[2];   // [H,H]
    const float* b_h  = (const float*)d_in[3];   // [H]
    float* out = (float*)d_out;                  // [T,B,H] outputs + [B,H] final

    // 1) Xp = X @ W_xh + b  -> written straight into d_out
    {
        dim3 grid(HID / G1_BN, (T_STEPS * BATCH) / G1_BM);
        xp_gemm<<<grid, 256>>>(X, W_xh, b_h, out);
    }

    // 2) full 512-step scan in one persistent kernel
    rnn_scan<<<SC_BLOCKS, 256>>>(W_hh, out);
}

// round 4
// speedup vs baseline: 5.0885x; 1.9239x over previous
#include <cuda_runtime.h>
#include <math.h>
#include <stdint.h>

#define T_STEPS 512
#define BATCH   64
#define IN_DIM  1024
#define HID     1024
#define BH      (BATCH * HID)          // 65536

// ---------- TF32 helpers ----------
__device__ __forceinline__ uint32_t f2tf32(float f) {
    uint32_t r;
    asm("cvt.rna.tf32.f32 %0, %1;" : "=r"(r) : "f"(f));
    return r;
}

__device__ __forceinline__ void mma_tf32(float c[4], const uint32_t a[4], const uint32_t b[2]) {
    asm("mma.sync.aligned.m16n8k8.row.col.f32.tf32.tf32.f32 "
        "{%0,%1,%2,%3}, {%4,%5,%6,%7}, {%8,%9}, {%0,%1,%2,%3};\n"
        : "+f"(c[0]), "+f"(c[1]), "+f"(c[2]), "+f"(c[3])
        : "r"(a[0]), "r"(a[1]), "r"(a[2]), "r"(a[3]), "r"(b[0]), "r"(b[1]));
}

// ============================================================
// Kernel 1: Xp = X @ W_xh + b   (TF32 mma, M=32768,N=1024,K=1024)
// Block 128m x 64n x BK=32. 256 thr = 8 warps (2m x 4n),
// warp tile 64m x 16n (4 m16-tiles x 2 n8-tiles).
// ============================================================
#define XA_STRIDE 36   // 32 + 4 pad  -> bank pattern 4r+c (conflict-free)
#define XB_STRIDE 72   // 64 + 8 pad  -> bank pattern 8k+n (conflict-free)

__global__ __launch_bounds__(256) void xp_gemm_tf32(const float* __restrict__ A,
                                                    const float* __restrict__ B,
                                                    const float* __restrict__ bias,
                                                    float* __restrict__ C) {
    __shared__ float As[128][XA_STRIDE];
    __shared__ float Bs[32][XB_STRIDE];
    __shared__ float biasS[64];

    const int bm  = blockIdx.y * 128;
    const int bn  = blockIdx.x * 64;
    const int tid = threadIdx.x;
    const int wid = tid >> 5;
    const int lane = tid & 31;
    const int gr  = lane >> 2;   // groupID 0..7
    const int tg  = lane & 3;    // threadID_in_group 0..3
    const int m_warp = wid & 1;        // 0..1 -> 64 rows
    const int n_warp = wid >> 1;       // 0..3 -> 16 cols

    if (tid < 64) biasS[tid] = bias[bn + tid];

    float acc[4][2][4] = {};   // [m16 tile][n8 tile][frag]

    for (int k0 = 0; k0 < IN_DIM; k0 += 32) {
        // Stage A tile 128x32 (4 float4 per thread)
        #pragma unroll
        for (int j = 0; j < 4; j++) {
            int idx = tid + j * 256;        // 0..1023
            int m   = idx >> 3;             // 0..127
            int kq  = (idx & 7) * 4;        // 0..28
            float4 v = *reinterpret_cast<const float4*>(
                &A[(size_t)(bm + m) * IN_DIM + k0 + kq]);
            *reinterpret_cast<float4*>(&As[m][kq]) = v;
        }
        // Stage B tile 32x64 (2 float4 per thread)
        #pragma unroll
        for (int j = 0; j < 2; j++) {
            int idx = tid + j * 256;        // 0..511
            int kk  = idx >> 4;             // 0..31
            int nq  = (idx & 15) * 4;       // 0..60
            float4 v = *reinterpret_cast<const float4*>(
                &B[(size_t)(k0 + kk) * HID + bn + nq]);
            *reinterpret_cast<float4*>(&Bs[kk][nq]) = v;
        }
        __syncthreads();

        #pragma unroll
        for (int ks = 0; ks < 4; ks++) {
            const int k8 = ks * 8;
            uint32_t bf[2][2];
            #pragma unroll
            for (int nt = 0; nt < 2; nt++) {
                int nn = n_warp * 16 + nt * 8 + gr;
                bf[nt][0] = f2tf32(Bs[k8 + tg][nn]);
                bf[nt][1] = f2tf32(Bs[k8 + tg + 4][nn]);
            }
            #pragma unroll
            for (int mt = 0; mt < 4; mt++) {
                int mb = m_warp * 64 + mt * 16;
                uint32_t af[4];
                af[0] = f2tf32(As[mb + gr][k8 + tg]);
                af[1] = f2tf32(As[mb + gr + 8][k8 + tg]);
                af[2] = f2tf32(As[mb + gr][k8 + tg + 4]);
                af[3] = f2tf32(As[mb + gr + 8][k8 + tg + 4]);
                mma_tf32(acc[mt][0], af, bf[0]);
                mma_tf32(acc[mt][1], af, bf[1]);
            }
        }
        __syncthreads();
    }

    // Epilogue: add bias, store (float2 per c0/c1 pair)
    #pragma unroll
    for (int mt = 0; mt < 4; mt++) {
        #pragma unroll
        for (int nt = 0; nt < 2; nt++) {
            int colL = n_warp * 16 + nt * 8 + 2 * tg;
            int row0 = bm + m_warp * 64 + mt * 16 + gr;
            float2 v0, v1;
            v0.x = acc[mt][nt][0] + biasS[colL];
            v0.y = acc[mt][nt][1] + biasS[colL + 1];
            v1.x = acc[mt][nt][2] + biasS[colL];
            v1.y = acc[mt][nt][3] + biasS[colL + 1];
            *reinterpret_cast<float2*>(&C[(size_t)row0 * HID + bn + colL]) = v0;
            *reinterpret_cast<float2*>(&C[(size_t)(row0 + 8) * HID + bn + colL]) = v1;
        }
    }
}

// ============================================================
// Persistent scan kernel (TF32 mma): all 512 steps, one launch.
// 128 blocks = 8 K-slices x 16 N-blocks. Block 64b x 64n x 128k.
// W_hh slice pre-loaded as TF32 B-fragments in REGISTERS (64/thr),
// once for all 512 steps. h staged in smem [b][k] per step.
// Warps: 2m x 4n, warp tile 32m x 16n.
// ============================================================
#define SC_BLOCKS 128
#define SC_KS     8
#define SC_KSL    128
#define H_STRIDE  132   // 128 + 4 pad -> bank pattern 4r+c

__device__ float    g_partial[SC_KS * BH];   // 2 MB scratch
__device__ unsigned g_bar  = 0;
__device__ unsigned g_done = 0;

__device__ __forceinline__ void grid_bar(unsigned* cnt, int nblocks) {
    __syncthreads();
    (*cnt)++;
    if (threadIdx.x == 0) {
        __threadfence();
        atomicAdd(&g_bar, 1u);
        unsigned target = (unsigned)nblocks * (*cnt);
        while (*((volatile unsigned*)&g_bar) < target) {
            __nanosleep(32);
        }
        __threadfence();
    }
    __syncthreads();
}

__global__ __launch_bounds__(256, 1) void rnn_scan(const float* __restrict__ W,
                                                   float* __restrict__ out) {
    __shared__ float hs[64][H_STRIDE];   // 33.8 KB: h chunk [b][k]

    const int tid  = threadIdx.x;
    const int bid  = blockIdx.x;
    const int ks   = bid >> 4;           // 0..7  K-slice
    const int nb   = bid & 15;           // 0..15 N-block
    const int k_base = ks * SC_KSL;
    const int n_base = nb * 64;
    const int wid  = tid >> 5;
    const int lane = tid & 31;
    const int gr   = lane >> 2;          // 0..7
    const int tg   = lane & 3;           // 0..3
    const int m_warp = wid & 1;          // 0..1  -> 32 rows
    const int n_warp = wid >> 1;         // 0..3  -> 16 cols

    // ---- Load W_hh slice as TF32 B-fragments into registers (once) ----
    // bfr[kstep][n8-tile][i]:  B[k][n], k = k_base+8*s+tg+4i, n = n_base+16*n_warp+8*nt+gr
    uint32_t bfr[16][2][2];
    #pragma unroll
    for (int s = 0; s < 16; s++) {
        #pragma unroll
        for (int nt = 0; nt < 2; nt++) {
            int n = n_base + n_warp * 16 + nt * 8 + gr;
            bfr[s][nt][0] = f2tf32(W[(size_t)(k_base + s * 8 + tg) * HID + n]);
            bfr[s][nt][1] = f2tf32(W[(size_t)(k_base + s * 8 + tg + 4) * HID + n]);
        }
    }

    unsigned barcnt = 0;

    // ---- Step 0: h_0 = tanh(Xp_0) ----
    {
        int base = (bid * 256 + tid) * 2;
        float2 v = *reinterpret_cast<float2*>(&out[base]);
        v.x = tanhf(v.x);
        v.y = tanhf(v.y);
        *reinterpret_cast<float2*>(&out[base]) = v;
    }
    grid_bar(&barcnt, SC_BLOCKS);

    for (int t = 1; t < T_STEPS; t++) {
        const float* h = out + (size_t)(t - 1) * BH;

        // ---- Stage h slice [64b x 128k] into smem (8 float4/thread) ----
        #pragma unroll
        for (int j = 0; j < 8; j++) {
            int idx = tid + j * 256;          // 0..2047
            int b   = idx >> 5;               // 0..63
            int kq  = (idx & 31) * 4;         // 0..124
            float4 v = *reinterpret_cast<const float4*>(
                &h[(size_t)b * HID + k_base + kq]);
            *reinterpret_cast<float4*>(&hs[b][kq]) = v;
        }
        __syncthreads();

        // ---- 512 mma: partial[64b x 64n] over this k-slice ----
        float acc[2][2][4] = {};   // [m16 tile][n8 tile][frag]
        #pragma unroll
        for (int s = 0; s < 16; s++) {
            const int k8 = s * 8;
            #pragma unroll
            for (int mt = 0; mt < 2; mt++) {
                int mb = m_warp * 32 + mt * 16;
                uint32_t af[4];
                af[0] = f2tf32(hs[mb + gr][k8 + tg]);
                af[1] = f2tf32(hs[mb + gr + 8][k8 + tg]);
                af[2] = f2tf32(hs[mb + gr][k8 + tg + 4]);
                af[3] = f2tf32(hs[mb + gr + 8][k8 + tg + 4]);
                mma_tf32(acc[mt][0], af, bfr[s][0]);
                mma_tf32(acc[mt][1], af, bfr[s][1]);
            }
        }

        // ---- Store partials (float2 pairs) ----
        float* gp = &g_partial[ks * BH];
        #pragma unroll
        for (int mt = 0; mt < 2; mt++) {
            #pragma unroll
            for (int nt = 0; nt < 2; nt++) {
                int colL = n_base + n_warp * 16 + nt * 8 + 2 * tg;
                int row0 = m_warp * 32 + mt * 16 + gr;
                float2 v0 = make_float2(acc[mt][nt][0], acc[mt][nt][1]);
                float2 v1 = make_float2(acc[mt][nt][2], acc[mt][nt][3]);
                *reinterpret_cast<float2*>(&gp[(size_t)row0 * HID + colL]) = v0;
                *reinterpret_cast<float2*>(&gp[(size_t)(row0 + 8) * HID + colL]) = v1;
            }
        }
        grid_bar(&barcnt, SC_BLOCKS);

        // ---- Phase B: reduce 8 partials + Xp, tanh, write out[t] ----
        {
            int base = (bid * 256 + tid) * 2;
            float* o = out + (size_t)t * BH;
            float2 xp = *reinterpret_cast<float2*>(&o[base]);
            float s0 = xp.x, s1 = xp.y;
            #pragma unroll
            for (int k2 = 0; k2 < SC_KS; k2++) {
                float2 p = *reinterpret_cast<const float2*>(&g_partial[k2 * BH + base]);
                s0 += p.x; s1 += p.y;
            }
            float2 r;
            r.x = tanhf(s0);
            r.y = tanhf(s1);
            *reinterpret_cast<float2*>(&o[base]) = r;
        }
        grid_bar(&barcnt, SC_BLOCKS);
    }

    // ---- Final state = out[T-1] -> tail ----
    {
        int base = (bid * 256 + tid) * 2;
        float2 v = *reinterpret_cast<const float2*>(
            &out[(size_t)(T_STEPS - 1) * BH + base]);
        *reinterpret_cast<float2*>(&out[(size_t)T_STEPS * BH + base]) = v;
    }

    // ---- Reset barrier state for graph replays ----
    __syncthreads();
    if (tid == 0) {
        unsigned d = atomicAdd(&g_done, 1u);
        if (d == (unsigned)(gridDim.x - 1)) {
            g_bar  = 0;
            g_done = 0;
            __threadfence();
        }
    }
}

// ============================================================
extern "C" void kernel_launch(void* const* d_in, const int* in_sizes, int n_in,
                              void* d_out, int out_size) {
    const float* X    = (const float*)d_in[0];   // [T,B,I]
    const float* W_xh = (const float*)d_in[1];   // [I,H]
    const float* W_hh = (const float*)d_in[2];   // [H,H]
    const float* b_h  = (const float*)d_in[3];   // [H]
    float* out = (float*)d_out;                  // [T,B,H] outputs + [B,H] final

    // 1) Xp = X @ W_xh + b  -> straight into d_out
    {
        dim3 grid(HID / 64, (T_STEPS * BATCH) / 128);
        xp_gemm_tf32<<<grid, 256>>>(X, W_xh, b_h, out);
    }

    // 2) full 512-step scan, persistent kernel
    rnn_scan<<<SC_BLOCKS, 256>>>(W_hh, out);
}

// round 6
// speedup vs baseline: 5.6114x; 1.1028x over previous
#include <cuda_runtime.h>
#include <math.h>
#include <stdint.h>

#define T_STEPS 512
#define BATCH   64
#define IN_DIM  1024
#define HID     1024
#define BH      (BATCH * HID)          // 65536

// ---------- TF32 helpers ----------
__device__ __forceinline__ uint32_t f2tf32(float f) {
    uint32_t r;
    asm("cvt.rna.tf32.f32 %0, %1;" : "=r"(r) : "f"(f));
    return r;
}

__device__ __forceinline__ void mma_tf32(float c[4], const uint32_t a[4], const uint32_t b[2]) {
    asm("mma.sync.aligned.m16n8k8.row.col.f32.tf32.tf32.f32 "
        "{%0,%1,%2,%3}, {%4,%5,%6,%7}, {%8,%9}, {%0,%1,%2,%3};\n"
        : "+f"(c[0]), "+f"(c[1]), "+f"(c[2]), "+f"(c[3])
        : "r"(a[0]), "r"(a[1]), "r"(a[2]), "r"(a[3]), "r"(b[0]), "r"(b[1]));
}

// ============================================================
// Kernel 1: Xp = X @ W_xh + b   (TF32 mma, M=32768,N=1024,K=1024)
// ============================================================
#define XA_STRIDE 36
#define XB_STRIDE 72

__global__ __launch_bounds__(256) void xp_gemm_tf32(const float* __restrict__ A,
                                                    const float* __restrict__ B,
                                                    const float* __restrict__ bias,
                                                    float* __restrict__ C) {
    __shared__ float As[128][XA_STRIDE];
    __shared__ float Bs[32][XB_STRIDE];
    __shared__ float biasS[64];

    const int bm  = blockIdx.y * 128;
    const int bn  = blockIdx.x * 64;
    const int tid = threadIdx.x;
    const int wid = tid >> 5;
    const int lane = tid & 31;
    const int gr  = lane >> 2;
    const int tg  = lane & 3;
    const int m_warp = wid & 1;
    const int n_warp = wid >> 1;

    if (tid < 64) biasS[tid] = bias[bn + tid];

    float acc[4][2][4] = {};

    for (int k0 = 0; k0 < IN_DIM; k0 += 32) {
        #pragma unroll
        for (int j = 0; j < 4; j++) {
            int idx = tid + j * 256;
            int m   = idx >> 3;
            int kq  = (idx & 7) * 4;
            float4 v = *reinterpret_cast<const float4*>(
                &A[(size_t)(bm + m) * IN_DIM + k0 + kq]);
            *reinterpret_cast<float4*>(&As[m][kq]) = v;
        }
        #pragma unroll
        for (int j = 0; j < 2; j++) {
            int idx = tid + j * 256;
            int kk  = idx >> 4;
            int nq  = (idx & 15) * 4;
            float4 v = *reinterpret_cast<const float4*>(
                &B[(size_t)(k0 + kk) * HID + bn + nq]);
            *reinterpret_cast<float4*>(&Bs[kk][nq]) = v;
        }
        __syncthreads();

        #pragma unroll
        for (int ks = 0; ks < 4; ks++) {
            const int k8 = ks * 8;
            uint32_t bf[2][2];
            #pragma unroll
            for (int nt = 0; nt < 2; nt++) {
                int nn = n_warp * 16 + nt * 8 + gr;
                bf[nt][0] = f2tf32(Bs[k8 + tg][nn]);
                bf[nt][1] = f2tf32(Bs[k8 + tg + 4][nn]);
            }
            #pragma unroll
            for (int mt = 0; mt < 4; mt++) {
                int mb = m_warp * 64 + mt * 16;
                uint32_t af[4];
                af[0] = f2tf32(As[mb + gr][k8 + tg]);
                af[1] = f2tf32(As[mb + gr + 8][k8 + tg]);
                af[2] = f2tf32(As[mb + gr][k8 + tg + 4]);
                af[3] = f2tf32(As[mb + gr + 8][k8 + tg + 4]);
                mma_tf32(acc[mt][0], af, bf[0]);
                mma_tf32(acc[mt][1], af, bf[1]);
            }
        }
        __syncthreads();
    }

    #pragma unroll
    for (int mt = 0; mt < 4; mt++) {
        #pragma unroll
        for (int nt = 0; nt < 2; nt++) {
            int colL = n_warp * 16 + nt * 8 + 2 * tg;
            int row0 = bm + m_warp * 64 + mt * 16 + gr;
            float2 v0, v1;
            v0.x = acc[mt][nt][0] + biasS[colL];
            v0.y = acc[mt][nt][1] + biasS[colL + 1];
            v1.x = acc[mt][nt][2] + biasS[colL];
            v1.y = acc[mt][nt][3] + biasS[colL + 1];
            *reinterpret_cast<float2*>(&C[(size_t)row0 * HID + bn + colL]) = v0;
            *reinterpret_cast<float2*>(&C[(size_t)(row0 + 8) * HID + bn + colL]) = v1;
        }
    }
}

// ============================================================
// Persistent scan kernel (TF32 mma), 128 blocks = 8 ksplits x 16 nblocks.
// Fast grid barrier: red.release arrival + ld.acquire poll, bounded
// backoff (nanosleep only after ~4K spins). Xp prefetched pre-barrier.
// ============================================================
#define SC_BLOCKS 128
#define SC_KS     8
#define SC_KSL    128
#define H_STRIDE  132

__device__ float    g_partial[SC_KS * BH];   // 2 MB scratch
__device__ unsigned g_bar  = 0;
__device__ unsigned g_done = 0;

__device__ __forceinline__ void grid_bar(unsigned* cnt, int nblocks) {
    __syncthreads();
    (*cnt)++;
    if (threadIdx.x == 0) {
        unsigned target = (unsigned)nblocks * (*cnt);
        // release-arrival: orders this block's prior global stores
        asm volatile("red.release.gpu.global.add.u32 [%0], %1;"
                     :: "l"(&g_bar), "r"(1u) : "memory");
        unsigned v;
        int spins = 0;
        do {
            asm volatile("ld.acquire.gpu.global.u32 %0, [%1];"
                         : "=r"(v) : "l"(&g_bar) : "memory");
            if (++spins > 4096) __nanosleep(64);   // pathological-case guard
        } while (v < target);
    }
    __syncthreads();
}

__global__ __launch_bounds__(256, 1) void rnn_scan(const float* __restrict__ W,
                                                   float* __restrict__ out) {
    __shared__ float hs[64][H_STRIDE];   // 33.8 KB: h chunk [b][k]

    const int tid  = threadIdx.x;
    const int bid  = blockIdx.x;
    const int ks   = bid >> 4;
    const int nb   = bid & 15;
    const int k_base = ks * SC_KSL;
    const int n_base = nb * 64;
    const int wid  = tid >> 5;
    const int lane = tid & 31;
    const int gr   = lane >> 2;
    const int tg   = lane & 3;
    const int m_warp = wid & 1;
    const int n_warp = wid >> 1;

    // ---- W_hh slice as TF32 B-fragments in registers (once for 512 steps) ----
    uint32_t bfr[16][2][2];
    #pragma unroll
    for (int s = 0; s < 16; s++) {
        #pragma unroll
        for (int nt = 0; nt < 2; nt++) {
            int n = n_base + n_warp * 16 + nt * 8 + gr;
            bfr[s][nt][0] = f2tf32(W[(size_t)(k_base + s * 8 + tg) * HID + n]);
            bfr[s][nt][1] = f2tf32(W[(size_t)(k_base + s * 8 + tg + 4) * HID + n]);
        }
    }

    unsigned barcnt = 0;
    const int pb_base = (bid * 256 + tid) * 2;   // phase-B element pair

    // ---- Step 0: h_0 = tanh(Xp_0) ----
    {
        float2 v = *reinterpret_cast<float2*>(&out[pb_base]);
        v.x = tanhf(v.x);
        v.y = tanhf(v.y);
        *reinterpret_cast<float2*>(&out[pb_base]) = v;
    }
    grid_bar(&barcnt, SC_BLOCKS);

    for (int t = 1; t < T_STEPS; t++) {
        const float* h = out + (size_t)(t - 1) * BH;
        float* o       = out + (size_t)t * BH;

        // ---- Stage h slice [64b x 128k] into smem ----
        #pragma unroll
        for (int j = 0; j < 8; j++) {
            int idx = tid + j * 256;
            int b   = idx >> 5;
            int kq  = (idx & 31) * 4;
            float4 v = *reinterpret_cast<const float4*>(
                &h[(size_t)b * HID + k_base + kq]);
            *reinterpret_cast<float4*>(&hs[b][kq]) = v;
        }
        __syncthreads();

        // ---- 512 mma: partial[64b x 64n] over this k-slice ----
        float acc[2][2][4] = {};
        #pragma unroll
        for (int s = 0; s < 16; s++) {
            const int k8 = s * 8;
            #pragma unroll
            for (int mt = 0; mt < 2; mt++) {
                int mb = m_warp * 32 + mt * 16;
                uint32_t af[4];
                af[0] = f2tf32(hs[mb + gr][k8 + tg]);
                af[1] = f2tf32(hs[mb + gr + 8][k8 + tg]);
                af[2] = f2tf32(hs[mb + gr][k8 + tg + 4]);
                af[3] = f2tf32(hs[mb + gr + 8][k8 + tg + 4]);
                mma_tf32(acc[mt][0], af, bfr[s][0]);
                mma_tf32(acc[mt][1], af, bfr[s][1]);
            }
        }

        // ---- Store partials ----
        float* gp = &g_partial[ks * BH];
        #pragma unroll
        for (int mt = 0; mt < 2; mt++) {
            #pragma unroll
            for (int nt = 0; nt < 2; nt++) {
                int colL = n_base + n_warp * 16 + nt * 8 + 2 * tg;
                int row0 = m_warp * 32 + mt * 16 + gr;
                float2 v0 = make_float2(acc[mt][nt][0], acc[mt][nt][1]);
                float2 v1 = make_float2(acc[mt][nt][2], acc[mt][nt][3]);
                *reinterpret_cast<float2*>(&gp[(size_t)row0 * HID + colL]) = v0;
                *reinterpret_cast<float2*>(&gp[(size_t)(row0 + 8) * HID + colL]) = v1;
            }
        }

        // ---- Prefetch Xp_t; force materialization BEFORE arrival so no
        //      in-flight load can observe phase-B writes. ----
        float2 xp = *reinterpret_cast<const float2*>(&o[pb_base]);
        asm volatile("" : "+f"(xp.x), "+f"(xp.y));

        grid_bar(&barcnt, SC_BLOCKS);

        // ---- Phase B: reduce 8 partials + Xp, tanh, write out[t] ----
        {
            float s0 = xp.x, s1 = xp.y;
            #pragma unroll
            for (int k2 = 0; k2 < SC_KS; k2++) {
                float2 p = *reinterpret_cast<const float2*>(&g_partial[k2 * BH + pb_base]);
                s0 += p.x; s1 += p.y;
            }
            float2 r;
            r.x = tanhf(s0);
            r.y = tanhf(s1);
            *reinterpret_cast<float2*>(&o[pb_base]) = r;
        }
        grid_bar(&barcnt, SC_BLOCKS);
    }

    // ---- Final state = out[T-1] -> tail ----
    {
        float2 v = *reinterpret_cast<const float2*>(
            &out[(size_t)(T_STEPS - 1) * BH + pb_base]);
        *reinterpret_cast<float2*>(&out[(size_t)T_STEPS * BH + pb_base]) = v;
    }

    // ---- Reset barrier state for graph replays ----
    __syncthreads();
    if (tid == 0) {
        unsigned d = atomicAdd(&g_done, 1u);
        if (d == (unsigned)(gridDim.x - 1)) {
            g_bar  = 0;
            g_done = 0;
            __threadfence();
        }
    }
}

// ============================================================
extern "C" void kernel_launch(void* const* d_in, const int* in_sizes, int n_in,
                              void* d_out, int out_size) {
    const float* X    = (const float*)d_in[0];
    const float* W_xh = (const float*)d_in[1];
    const float* W_hh = (const float*)d_in[2];
    const float* b_h  = (const float*)d_in[3];
    float* out = (float*)d_out;

    {
        dim3 grid(HID / 64, (T_STEPS * BATCH) / 128);
        xp_gemm_tf32<<<grid, 256>>>(X, W_xh, b_h, out);
    }
    rnn_scan<<<SC_BLOCKS, 256>>>(W_hh, out);
}

// round 7
// speedup vs baseline: 5.7435x; 1.0235x over previous
#include <cuda_runtime.h>
#include <math.h>
#include <stdint.h>

#define T_STEPS 512
#define BATCH   64
#define IN_DIM  1024
#define HID     1024
#define BH      (BATCH * HID)          // 65536

// ---------- TF32 helpers ----------
__device__ __forceinline__ uint32_t f2tf32(float f) {
    uint32_t r;
    asm("cvt.rna.tf32.f32 %0, %1;" : "=r"(r) : "f"(f));
    return r;
}

__device__ __forceinline__ float tanh_fast(float x) {
    float y;
    asm("tanh.approx.f32 %0, %1;" : "=f"(y) : "f"(x));
    return y;
}

__device__ __forceinline__ void mma_tf32(float c[4], const uint32_t a[4], const uint32_t b[2]) {
    asm("mma.sync.aligned.m16n8k8.row.col.f32.tf32.tf32.f32 "
        "{%0,%1,%2,%3}, {%4,%5,%6,%7}, {%8,%9}, {%0,%1,%2,%3};\n"
        : "+f"(c[0]), "+f"(c[1]), "+f"(c[2]), "+f"(c[3])
        : "r"(a[0]), "r"(a[1]), "r"(a[2]), "r"(a[3]), "r"(b[0]), "r"(b[1]));
}

// ============================================================
// Kernel 1: Xp = X @ W_xh + b  (TF32 mma; smem holds PRE-CONVERTED
// tf32 bits so the mainloop has zero cvt instructions)
// ============================================================
#define XA_STRIDE 36
#define XB_STRIDE 72

__global__ __launch_bounds__(256) void xp_gemm_tf32(const float* __restrict__ A,
                                                    const float* __restrict__ B,
                                                    const float* __restrict__ bias,
                                                    float* __restrict__ C) {
    __shared__ uint32_t As[128][XA_STRIDE];
    __shared__ uint32_t Bs[32][XB_STRIDE];
    __shared__ float biasS[64];

    const int bm  = blockIdx.y * 128;
    const int bn  = blockIdx.x * 64;
    const int tid = threadIdx.x;
    const int wid = tid >> 5;
    const int lane = tid & 31;
    const int gr  = lane >> 2;
    const int tg  = lane & 3;
    const int m_warp = wid & 1;
    const int n_warp = wid >> 1;

    if (tid < 64) biasS[tid] = bias[bn + tid];

    float acc[4][2][4] = {};

    for (int k0 = 0; k0 < IN_DIM; k0 += 32) {
        #pragma unroll
        for (int j = 0; j < 4; j++) {
            int idx = tid + j * 256;
            int m   = idx >> 3;
            int kq  = (idx & 7) * 4;
            float4 v = *reinterpret_cast<const float4*>(
                &A[(size_t)(bm + m) * IN_DIM + k0 + kq]);
            uint4 w = make_uint4(f2tf32(v.x), f2tf32(v.y), f2tf32(v.z), f2tf32(v.w));
            *reinterpret_cast<uint4*>(&As[m][kq]) = w;
        }
        #pragma unroll
        for (int j = 0; j < 2; j++) {
            int idx = tid + j * 256;
            int kk  = idx >> 4;
            int nq  = (idx & 15) * 4;
            float4 v = *reinterpret_cast<const float4*>(
                &B[(size_t)(k0 + kk) * HID + bn + nq]);
            uint4 w = make_uint4(f2tf32(v.x), f2tf32(v.y), f2tf32(v.z), f2tf32(v.w));
            *reinterpret_cast<uint4*>(&Bs[kk][nq]) = w;
        }
        __syncthreads();

        #pragma unroll
        for (int ks = 0; ks < 4; ks++) {
            const int k8 = ks * 8;
            uint32_t bf[2][2];
            #pragma unroll
            for (int nt = 0; nt < 2; nt++) {
                int nn = n_warp * 16 + nt * 8 + gr;
                bf[nt][0] = Bs[k8 + tg][nn];
                bf[nt][1] = Bs[k8 + tg + 4][nn];
            }
            #pragma unroll
            for (int mt = 0; mt < 4; mt++) {
                int mb = m_warp * 64 + mt * 16;
                uint32_t af[4];
                af[0] = As[mb + gr][k8 + tg];
                af[1] = As[mb + gr + 8][k8 + tg];
                af[2] = As[mb + gr][k8 + tg + 4];
                af[3] = As[mb + gr + 8][k8 + tg + 4];
                mma_tf32(acc[mt][0], af, bf[0]);
                mma_tf32(acc[mt][1], af, bf[1]);
            }
        }
        __syncthreads();
    }

    #pragma unroll
    for (int mt = 0; mt < 4; mt++) {
        #pragma unroll
        for (int nt = 0; nt < 2; nt++) {
            int colL = n_warp * 16 + nt * 8 + 2 * tg;
            int row0 = bm + m_warp * 64 + mt * 16 + gr;
            float2 v0, v1;
            v0.x = acc[mt][nt][0] + biasS[colL];
            v0.y = acc[mt][nt][1] + biasS[colL + 1];
            v1.x = acc[mt][nt][2] + biasS[colL];
            v1.y = acc[mt][nt][3] + biasS[colL + 1];
            *reinterpret_cast<float2*>(&C[(size_t)row0 * HID + bn + colL]) = v0;
            *reinterpret_cast<float2*>(&C[(size_t)(row0 + 8) * HID + bn + colL]) = v1;
        }
    }
}

// ============================================================
// Persistent scan kernel. Permuted-K mapping so A-fragments come
// from LDS.128 (4x fewer LDS insts); smem holds tf32 bits.
// For mma pair (u, p): k-slot tg -> col 16u+4tg+2p, slot tg+4 ->
// col 16u+4tg+2p+1. B-fragments (registers) indexed to match.
// ============================================================
#define SC_BLOCKS 128
#define SC_KS     8
#define SC_KSL    128
#define H_STRIDE  144   // 144 mod 32 == 16 -> conflict-free LDS.128

__device__ float    g_partial[SC_KS * BH];   // 2 MB scratch
__device__ unsigned g_bar  = 0;
__device__ unsigned g_done = 0;

__device__ __forceinline__ void grid_bar(unsigned* cnt, int nblocks) {
    __syncthreads();
    (*cnt)++;
    if (threadIdx.x == 0) {
        unsigned target = (unsigned)nblocks * (*cnt);
        asm volatile("red.release.gpu.global.add.u32 [%0], %1;"
                     :: "l"(&g_bar), "r"(1u) : "memory");
        unsigned v;
        int spins = 0;
        do {
            asm volatile("ld.acquire.gpu.global.u32 %0, [%1];"
                         : "=r"(v) : "l"(&g_bar) : "memory");
            if (++spins > 4096) __nanosleep(64);
        } while (v < target);
    }
    __syncthreads();
}

__global__ __launch_bounds__(256, 1) void rnn_scan(const float* __restrict__ W,
                                                   float* __restrict__ out) {
    __shared__ uint32_t hs[64][H_STRIDE];   // 36.9 KB, tf32 bits [b][k]

    const int tid  = threadIdx.x;
    const int bid  = blockIdx.x;
    const int ks   = bid >> 4;
    const int nb   = bid & 15;
    const int k_base = ks * SC_KSL;
    const int n_base = nb * 64;
    const int wid  = tid >> 5;
    const int lane = tid & 31;
    const int gr   = lane >> 2;
    const int tg   = lane & 3;
    const int m_warp = wid & 1;
    const int n_warp = wid >> 1;

    // ---- W_hh B-fragments, permuted-K indexing, once for 512 steps ----
    // bfr[u][p][nt][i]: W[k_base + 16u + 4tg + 2p + i][n]
    uint32_t bfr[8][2][2][2];
    #pragma unroll
    for (int u = 0; u < 8; u++) {
        #pragma unroll
        for (int p = 0; p < 2; p++) {
            #pragma unroll
            for (int nt = 0; nt < 2; nt++) {
                int n = n_base + n_warp * 16 + nt * 8 + gr;
                int kk = k_base + 16 * u + 4 * tg + 2 * p;
                bfr[u][p][nt][0] = f2tf32(W[(size_t)kk * HID + n]);
                bfr[u][p][nt][1] = f2tf32(W[(size_t)(kk + 1) * HID + n]);
            }
        }
    }

    unsigned barcnt = 0;
    const int pb2 = (bid * 256 + tid) * 2;   // full-thread float2 index
    const int pb4 = (bid * 128 + tid) * 4;   // half-thread float4 index

    // ---- Step 0: h_0 = tanh(Xp_0) ----
    {
        float2 v = *reinterpret_cast<float2*>(&out[pb2]);
        v.x = tanh_fast(v.x);
        v.y = tanh_fast(v.y);
        *reinterpret_cast<float2*>(&out[pb2]) = v;
    }
    grid_bar(&barcnt, SC_BLOCKS);

    for (int t = 1; t < T_STEPS; t++) {
        const float* h = out + (size_t)(t - 1) * BH;
        float* o       = out + (size_t)t * BH;

        // ---- Stage h slice [64b x 128k], converting to tf32 ----
        #pragma unroll
        for (int j = 0; j < 8; j++) {
            int idx = tid + j * 256;
            int b   = idx >> 5;
            int kq  = (idx & 31) * 4;
            float4 v = *reinterpret_cast<const float4*>(
                &h[(size_t)b * HID + k_base + kq]);
            uint4 w = make_uint4(f2tf32(v.x), f2tf32(v.y), f2tf32(v.z), f2tf32(v.w));
            *reinterpret_cast<uint4*>(&hs[b][kq]) = w;
        }
        __syncthreads();

        // ---- 64 mma/thread-warp, A-frags via LDS.128 (permuted K) ----
        float acc[2][2][4] = {};
        #pragma unroll
        for (int u = 0; u < 8; u++) {
            const int kc = 16 * u + 4 * tg;
            #pragma unroll
            for (int mt = 0; mt < 2; mt++) {
                int row = m_warp * 32 + mt * 16 + gr;
                uint4 va = *reinterpret_cast<const uint4*>(&hs[row][kc]);
                uint4 vb = *reinterpret_cast<const uint4*>(&hs[row + 8][kc]);
                uint32_t afA[4] = {va.x, vb.x, va.y, vb.y};
                uint32_t afB[4] = {va.z, vb.z, va.w, vb.w};
                mma_tf32(acc[mt][0], afA, bfr[u][0][0]);
                mma_tf32(acc[mt][1], afA, bfr[u][0][1]);
                mma_tf32(acc[mt][0], afB, bfr[u][1][0]);
                mma_tf32(acc[mt][1], afB, bfr[u][1][1]);
            }
        }

        // ---- Store partials ----
        float* gp = &g_partial[ks * BH];
        #pragma unroll
        for (int mt = 0; mt < 2; mt++) {
            #pragma unroll
            for (int nt = 0; nt < 2; nt++) {
                int colL = n_base + n_warp * 16 + nt * 8 + 2 * tg;
                int row0 = m_warp * 32 + mt * 16 + gr;
                float2 v0 = make_float2(acc[mt][nt][0], acc[mt][nt][1]);
                float2 v1 = make_float2(acc[mt][nt][2], acc[mt][nt][3]);
                *reinterpret_cast<float2*>(&gp[(size_t)row0 * HID + colL]) = v0;
                *reinterpret_cast<float2*>(&gp[(size_t)(row0 + 8) * HID + colL]) = v1;
            }
        }

        // ---- Prefetch Xp_t (half threads, float4); materialize pre-arrival ----
        float4 xp = make_float4(0.f, 0.f, 0.f, 0.f);
        if (tid < 128) {
            xp = *reinterpret_cast<const float4*>(&o[pb4]);
            asm volatile("" : "+f"(xp.x), "+f"(xp.y), "+f"(xp.z), "+f"(xp.w));
        }

        grid_bar(&barcnt, SC_BLOCKS);

        // ---- Phase B: reduce 8 partials + Xp, tanh, write out[t] ----
        if (tid < 128) {
            float s0 = xp.x, s1 = xp.y, s2 = xp.z, s3 = xp.w;
            #pragma unroll
            for (int k2 = 0; k2 < SC_KS; k2++) {
                float4 p = *reinterpret_cast<const float4*>(&g_partial[k2 * BH + pb4]);
                s0 += p.x; s1 += p.y; s2 += p.z; s3 += p.w;
            }
            float4 r;
            r.x = tanh_fast(s0);
            r.y = tanh_fast(s1);
            r.z = tanh_fast(s2);
            r.w = tanh_fast(s3);
            *reinterpret_cast<float4*>(&o[pb4]) = r;
        }
        grid_bar(&barcnt, SC_BLOCKS);
    }

    // ---- Final state = out[T-1] -> tail ----
    {
        float2 v = *reinterpret_cast<const float2*>(
            &out[(size_t)(T_STEPS - 1) * BH + pb2]);
        *reinterpret_cast<float2*>(&out[(size_t)T_STEPS * BH + pb2]) = v;
    }

    // ---- Reset barrier state for graph replays ----
    __syncthreads();
    if (tid == 0) {
        unsigned d = atomicAdd(&g_done, 1u);
        if (d == (unsigned)(gridDim.x - 1)) {
            g_bar  = 0;
            g_done = 0;
            __threadfence();
        }
    }
}

// ============================================================
extern "C" void kernel_launch(void* const* d_in, const int* in_sizes, int n_in,
                              void* d_out, int out_size) {
    const float* X    = (const float*)d_in[0];
    const float* W_xh = (const float*)d_in[1];
    const float* W_hh = (const float*)d_in[2];
    const float* b_h  = (const float*)d_in[3];
    float* out = (float*)d_out;

    {
        dim3 grid(HID / 64, (T_STEPS * BATCH) / 128);
        xp_gemm_tf32<<<grid, 256>>>(X, W_xh, b_h, out);
    }
    rnn_scan<<<SC_BLOCKS, 256>>>(W_hh, out);
}